// round 4
// baseline (speedup 1.0000x reference)
#include <cuda_runtime.h>
#include <cstdint>
#include <cstddef>

#define Bb 512
#define Ss 2048
#define Vv 29
#define Hh 128
#define NB 2            // batch rows per block
#define NTHREADS 256
#define KTOT 157        // 128 (h) + 29 (x)
#define KQ 40           // k-range per quarter (4*40 = 160 >= 157, tail zero-padded)
#define CLEN 160        // padded concat vector length

using ull = unsigned long long;

__device__ __forceinline__ ull pack2(float lo, float hi) {
    ull r; asm("mov.b64 %0, {%1, %2};" : "=l"(r) : "f"(lo), "f"(hi)); return r;
}
__device__ __forceinline__ float2 unpack2(ull v) {
    float2 r; asm("mov.b64 {%0, %1}, %2;" : "=f"(r.x), "=f"(r.y) : "l"(v)); return r;
}
__device__ __forceinline__ ull fma2(ull a, ull b, ull c) {
    ull d; asm("fma.rn.f32x2 %0, %1, %2, %3;" : "=l"(d) : "l"(a), "l"(b), "l"(c)); return d;
}
__device__ __forceinline__ ull add2(ull a, ull b) {
    ull d; asm("add.rn.f32x2 %0, %1, %2;" : "=l"(d) : "l"(a), "l"(b)); return d;
}
__device__ __forceinline__ ull shfl_bfly2(ull v, int m) {
    uint32_t lo = (uint32_t)v, hi = (uint32_t)(v >> 32);
    lo = __shfl_xor_sync(0xffffffffu, lo, m);
    hi = __shfl_xor_sync(0xffffffffu, hi, m);
    return (ull)lo | ((ull)hi << 32);
}

// Accurate tanh via MUFU.EX2: abs error ~1e-7, safe for 2048-step recurrence.
__device__ __forceinline__ float tanh_acc(float xx) {
    float ax = fabsf(xx);
    float e  = __expf(-2.0f * ax);
    float r  = __fdividef(1.0f - e, 1.0f + e);
    return copysignf(r, xx);
}

__global__ void __launch_bounds__(NTHREADS, 2) rnn_ae_kernel(
    const float* __restrict__ x,
    const float* __restrict__ We_ih, const float* __restrict__ We_hh,
    const float* __restrict__ be_ih, const float* __restrict__ be_hh,
    const float* __restrict__ Wd_ih, const float* __restrict__ Wd_hh,
    const float* __restrict__ bd_ih, const float* __restrict__ bd_hh,
    float* __restrict__ out)
{
    // Double-buffered concat state, duplicated (v,v) fp32 pairs:
    // c2[buf][b][k]: k<128 -> h[k], 128..156 -> x[b,t,k-128], 157..159 -> permanent zeros.
    __shared__ __align__(16) ull c2[2][NB][CLEN];
    __shared__ float biasf[Hh];

    const int tid   = threadIdx.x;
    const int lane  = tid & 31;
    const int warp  = tid >> 5;         // 0..7 = jphi
    const int jplo  = lane & 7;
    const int q     = lane >> 3;        // k-quarter (2 bits, lane bits 3..4)
    const int jp    = warp * 8 + jplo;  // output pair index: h units 2jp, 2jp+1
    const int bbase = blockIdx.x * NB;
    const int k0    = q * KQ;

    // ---- recurrent weights -> registers, packed as (row 2jp, row 2jp+1) pairs ----
    ull w2[KQ];
    {
        const int j0 = 2 * jp, j1 = j0 + 1;
        #pragma unroll
        for (int kk = 0; kk < KQ; kk++) {
            int k = k0 + kk;
            float a0 = 0.f, a1 = 0.f;
            if (k < Hh)        { a0 = We_hh[j0 * Hh + k];        a1 = We_hh[j1 * Hh + k]; }
            else if (k < KTOT) { a0 = We_ih[j0 * Vv + (k - Hh)]; a1 = We_ih[j1 * Vv + (k - Hh)]; }
            w2[kk] = pack2(a0, a1);
        }
    }
    if (tid < Hh) biasf[tid] = be_ih[tid] + be_hh[tid];

    for (int i = tid; i < 2 * NB * CLEN; i += NTHREADS) (&c2[0][0][0])[i] = 0ull;
    __syncthreads();

    // x-prefetch duty: tids 0..57 each own one (row, vocab) slot
    const bool xact = (tid < NB * Vv);
    const int  xb   = xact ? (tid / Vv) : 0;
    const int  xv   = xact ? (tid % Vv) : 0;
    const float* xptr = x + (size_t)(bbase + xb) * (Ss * Vv) + xv;
    float xr = 0.f;
    if (xact) {
        float x0 = __ldg(xptr);
        c2[0][xb][Hh + xv] = pack2(x0, x0);
        xr = __ldg(xptr + Vv);          // x[t=1]
    }
    __syncthreads();

    // ================= encoder: 2048 sequential steps, 1 barrier each =================
    #pragma unroll 1
    for (int t = 0; t < Ss; t++) {
        const int cur = t & 1, nxt = cur ^ 1;

        // stage x[t+1] into the buffer step t+1 will read; start fetch of x[t+2]
        if (xact) {
            if (t + 1 < Ss) c2[nxt][xb][Hh + xv] = pack2(xr, xr);
            if (t + 2 < Ss) xr = __ldg(xptr + (size_t)(t + 2) * Vv);
        }

        ull acc0 = 0ull, acc1 = 0ull;
        const ulonglong2* a0p = reinterpret_cast<const ulonglong2*>(&c2[cur][0][k0]);
        const ulonglong2* a1p = reinterpret_cast<const ulonglong2*>(&c2[cur][1][k0]);
        #pragma unroll
        for (int g = 0; g < KQ / 2; g++) {
            ulonglong2 v0 = a0p[g];
            ulonglong2 v1 = a1p[g];
            acc0 = fma2(w2[2 * g],     v0.x, acc0);
            acc1 = fma2(w2[2 * g],     v1.x, acc1);
            acc0 = fma2(w2[2 * g + 1], v0.y, acc0);
            acc1 = fma2(w2[2 * g + 1], v1.y, acc1);
        }

        // butterfly-reduce the 4 q-partials (lane bits 3,4) for both rows
        ull s0 = acc0, s1 = acc1;
        s0 = add2(s0, shfl_bfly2(s0, 8));  s0 = add2(s0, shfl_bfly2(s0, 16));
        s1 = add2(s1, shfl_bfly2(s1, 8));  s1 = add2(s1, shfl_bfly2(s1, 16));

        // each lane finishes one scalar: half = q&1, row = q>>1
        {
            const int half = q & 1;
            const int row  = q >> 1;
            float2 f = unpack2(row ? s1 : s0);
            float  v = (half ? f.y : f.x) + biasf[2 * jp + half];
            float  tv = tanh_acc(v);
            c2[nxt][row][2 * jp + half] = pack2(tv, tv);
        }
        __syncthreads();
    }

    // ================= decoder: warp-per-batch-row, shuffle-broadcast h =================
    // Warp wp (< NB) owns batch row bbase+wp; lane = vocab unit. No smem, no barriers.
    const int wp = warp;
    if (wp >= NB) return;

    const bool act = (lane < Vv);
    float wrow[Vv];
    #pragma unroll
    for (int k = 0; k < Vv; k++) wrow[k] = 0.f;

    float dec_in = 0.f;
    float* op = out;
    if (act) {
        #pragma unroll
        for (int k = 0; k < Vv; k++) wrow[k] = __ldg(&Wd_hh[lane * Vv + k]);
        // dec_in = encoded @ Wd_ih[lane]^T + bd_ih + bd_hh (constant across steps).
        // Final encoder h is in c2[0] (step 2047 wrote buffer (2047+1)&1 = 0).
        const float* hc = reinterpret_cast<const float*>(&c2[0][wp][0]); // lo halves
        const float* wi = Wd_ih + (size_t)lane * Hh;
        float a0 = bd_ih[lane] + bd_hh[lane], a1 = 0.f, a2 = 0.f, a3 = 0.f;
        #pragma unroll
        for (int k = 0; k < Hh; k += 4) {
            a0 += hc[2 * (k + 0)] * __ldg(wi + k + 0);
            a1 += hc[2 * (k + 1)] * __ldg(wi + k + 1);
            a2 += hc[2 * (k + 2)] * __ldg(wi + k + 2);
            a3 += hc[2 * (k + 3)] * __ldg(wi + k + 3);
        }
        dec_in = (a0 + a1) + (a2 + a3);
        op = out + (size_t)(bbase + wp) * (Ss * Vv) + lane;
    }

    float hval = 0.f;   // inactive lanes stay exactly 0 (wrow=0, dec_in=0 -> tanh(0)=0)
    #pragma unroll 1
    for (int s = 0; s < Ss; s++) {
        float a0 = dec_in, a1 = 0.f, a2 = 0.f, a3 = 0.f;
        #pragma unroll
        for (int k = 0; k < 28; k += 4) {
            a0 += __shfl_sync(0xffffffffu, hval, k + 0) * wrow[k + 0];
            a1 += __shfl_sync(0xffffffffu, hval, k + 1) * wrow[k + 1];
            a2 += __shfl_sync(0xffffffffu, hval, k + 2) * wrow[k + 2];
            a3 += __shfl_sync(0xffffffffu, hval, k + 3) * wrow[k + 3];
        }
        a0 += __shfl_sync(0xffffffffu, hval, 28) * wrow[28];
        hval = tanh_acc((a0 + a1) + (a2 + a3));
        if (act) op[(size_t)s * Vv] = hval;
    }
}

extern "C" void kernel_launch(void* const* d_in, const int* in_sizes, int n_in,
                              void* d_out, int out_size) {
    (void)in_sizes; (void)n_in; (void)out_size;
    rnn_ae_kernel<<<Bb / NB, NTHREADS>>>(
        (const float*)d_in[0],  // x
        (const float*)d_in[1],  // We_ih
        (const float*)d_in[2],  // We_hh
        (const float*)d_in[3],  // be_ih
        (const float*)d_in[4],  // be_hh
        (const float*)d_in[5],  // Wd_ih
        (const float*)d_in[6],  // Wd_hh
        (const float*)d_in[7],  // bd_ih
        (const float*)d_in[8],  // bd_hh
        (float*)d_out);
}

// round 14
// speedup vs baseline: 1.1826x; 1.1826x over previous
#include <cuda_runtime.h>
#include <cstdint>
#include <cstddef>

#define Bb 512
#define Ss 2048
#define Vv 29
#define Hh 128
#define NB 2            // batch rows per block
#define NTHREADS 256
#define KTOT 157        // 128 (h) + 29 (x)
#define KQ 10           // k-range per 16-way slice (16*10 = 160 >= 157, tail zero-padded)
#define NPAIR 4         // output pairs per thread
#define CLEN 160        // padded concat vector length

using ull = unsigned long long;

__device__ __forceinline__ ull pack2(float lo, float hi) {
    ull r; asm("mov.b64 %0, {%1, %2};" : "=l"(r) : "f"(lo), "f"(hi)); return r;
}
__device__ __forceinline__ float2 unpack2(ull v) {
    float2 r; asm("mov.b64 {%0, %1}, %2;" : "=f"(r.x), "=f"(r.y) : "l"(v)); return r;
}
__device__ __forceinline__ ull fma2(ull a, ull b, ull c) {
    ull d; asm("fma.rn.f32x2 %0, %1, %2, %3;" : "=l"(d) : "l"(a), "l"(b), "l"(c)); return d;
}
__device__ __forceinline__ ull add2(ull a, ull b) {
    ull d; asm("add.rn.f32x2 %0, %1, %2;" : "=l"(d) : "l"(a), "l"(b)); return d;
}
__device__ __forceinline__ ull shfl_bfly2(ull v, int m) {
    uint32_t lo = (uint32_t)v, hi = (uint32_t)(v >> 32);
    lo = __shfl_xor_sync(0xffffffffu, lo, m);
    hi = __shfl_xor_sync(0xffffffffu, hi, m);
    return (ull)lo | ((ull)hi << 32);
}

// Accurate tanh via MUFU.EX2: abs error ~1e-7, safe for 2048-step recurrence.
__device__ __forceinline__ float tanh_acc(float xx) {
    float ax = fabsf(xx);
    float e  = __expf(-2.0f * ax);
    float r  = __fdividef(1.0f - e, 1.0f + e);
    return copysignf(r, xx);
}

__global__ void __launch_bounds__(NTHREADS, 2) rnn_ae_kernel(
    const float* __restrict__ x,
    const float* __restrict__ We_ih, const float* __restrict__ We_hh,
    const float* __restrict__ be_ih, const float* __restrict__ be_hh,
    const float* __restrict__ Wd_ih, const float* __restrict__ Wd_hh,
    const float* __restrict__ bd_ih, const float* __restrict__ bd_hh,
    float* __restrict__ out)
{
    // Double-buffered concat state, duplicated (v,v) fp32 pairs:
    // c2[buf][b][k]: k<128 -> h[k], 128..156 -> x[b,t,k-128], 157..159 -> permanent zeros.
    __shared__ __align__(16) ull c2[2][NB][CLEN];

    const int tid   = threadIdx.x;
    const int lane  = tid & 31;
    const int warp  = tid >> 5;        // jg_hi (3 bits)
    const int jg_lo = lane & 1;
    const int q     = lane >> 1;       // k-slice index, 0..15 (lane bits 1..4)
    const int jg    = warp * 2 + jg_lo;            // j-group 0..15 (4 pairs each)
    const int k0    = q * KQ;
    const int qb0   = q & 1, qb1 = (q >> 1) & 1, qb2 = (q >> 2) & 1, qb3 = (q >> 3) & 1;
    const int p_own = 2 * qb1 + qb2;   // which of my 4 pairs I own post-reduce
    const int r_own = qb0;             // which row
    const int half  = qb3;             // which scalar of the pair
    const int hidx  = 8 * jg + 2 * p_own + half;   // h unit index 0..127
    const int bbase = blockIdx.x * NB;

    // ---- recurrent weights -> registers: 4 pairs x 10 k = 40 packed ulls ----
    ull w2[NPAIR][KQ];
    #pragma unroll
    for (int p = 0; p < NPAIR; p++) {
        const int j0 = 2 * (jg * NPAIR + p), j1 = j0 + 1;
        #pragma unroll
        for (int kk = 0; kk < KQ; kk++) {
            int k = k0 + kk;
            float a0 = 0.f, a1 = 0.f;
            if (k < Hh)        { a0 = We_hh[j0 * Hh + k];        a1 = We_hh[j1 * Hh + k]; }
            else if (k < KTOT) { a0 = We_ih[j0 * Vv + (k - Hh)]; a1 = We_ih[j1 * Vv + (k - Hh)]; }
            w2[p][kk] = pack2(a0, a1);
        }
    }
    const float bias_me = be_ih[hidx] + be_hh[hidx];

    for (int i = tid; i < 2 * NB * CLEN; i += NTHREADS) (&c2[0][0][0])[i] = 0ull;
    __syncthreads();

    // x-prefetch duty: tids 0..57 each own one (row, vocab) slot
    const bool xact = (tid < NB * Vv);
    const int  xb   = xact ? (tid / Vv) : 0;
    const int  xv   = xact ? (tid % Vv) : 0;
    const float* xptr = x + (size_t)(bbase + xb) * (Ss * Vv) + xv;
    float xr = 0.f;
    if (xact) {
        float x0 = __ldg(xptr);
        c2[0][xb][Hh + xv] = pack2(x0, x0);
        xr = __ldg(xptr + Vv);          // x[t=1]
    }
    __syncthreads();

    // ================= encoder: 2048 sequential steps, 1 barrier each =================
    #pragma unroll 1
    for (int t = 0; t < Ss; t++) {
        const int cur = t & 1, nxt = cur ^ 1;

        // start the long-latency fetch of x[t+2] now; STAGE x[t+1] (xstage) later,
        // after the FMA-phase LDS reads, so no STS sits above them.
        float xstage = xr;
        if (xact && t + 2 < Ss) xr = __ldg(xptr + (size_t)(t + 2) * Vv);

        // ---- FMA phase: 10 LDS.128, 80 fma2 (4 pairs x 10 k x 2 rows) ----
        ull acc[NPAIR][2];
        #pragma unroll
        for (int p = 0; p < NPAIR; p++) { acc[p][0] = 0ull; acc[p][1] = 0ull; }

        const ulonglong2* a0p = reinterpret_cast<const ulonglong2*>(&c2[cur][0][k0]);
        const ulonglong2* a1p = reinterpret_cast<const ulonglong2*>(&c2[cur][1][k0]);
        #pragma unroll
        for (int g = 0; g < KQ / 2; g++) {
            ulonglong2 v0 = a0p[g];
            ulonglong2 v1 = a1p[g];
            #pragma unroll
            for (int p = 0; p < NPAIR; p++) {
                acc[p][0] = fma2(w2[p][2 * g],     v0.x, acc[p][0]);
                acc[p][0] = fma2(w2[p][2 * g + 1], v0.y, acc[p][0]);
                acc[p][1] = fma2(w2[p][2 * g],     v1.x, acc[p][1]);
                acc[p][1] = fma2(w2[p][2 * g + 1], v1.y, acc[p][1]);
            }
        }

        // stage x[t+1] into the buffer step t+1 will read (after all LDS of cur)
        if (xact && t + 1 < Ss) c2[nxt][xb][Hh + xv] = pack2(xstage, xstage);

        // ---- 4-stage butterfly exchange-reduce over the 16 k-slices ----
        // stage 1 (mask 2): fold row dimension; lane keeps row r_own = qb0
        ull s1[NPAIR];
        #pragma unroll
        for (int p = 0; p < NPAIR; p++) {
            ull snd = qb0 ? acc[p][0] : acc[p][1];
            ull kp  = qb0 ? acc[p][1] : acc[p][0];
            s1[p] = add2(kp, shfl_bfly2(snd, 2));
        }
        // stage 2 (mask 4): fold p_hi; qb1 selects {2,3} vs {0,1}
        ull s2[2];
        #pragma unroll
        for (int i = 0; i < 2; i++) {
            ull snd = qb1 ? s1[i]     : s1[i + 2];
            ull kp  = qb1 ? s1[i + 2] : s1[i];
            s2[i] = add2(kp, shfl_bfly2(snd, 4));
        }
        // stage 3 (mask 8): fold p_lo; qb2 selects which of the remaining two
        {
            ull snd = qb2 ? s2[0] : s2[1];
            ull kp  = qb2 ? s2[1] : s2[0];
            ull s3  = add2(kp, shfl_bfly2(snd, 8));
            // stage 4 (mask 16): final halving; both partners keep the full sum
            ull s4  = add2(s3, shfl_bfly2(s3, 16));

            float2 f = unpack2(s4);
            float  v = (half ? f.y : f.x) + bias_me;
            float  tv = tanh_acc(v);
            c2[nxt][r_own][hidx] = pack2(tv, tv);
        }
        __syncthreads();
    }

    // ================= decoder: warp-per-batch-row, shuffle-broadcast h =================
    // Warp wp (< NB) owns batch row bbase+wp; lane = vocab unit. No smem, no barriers.
    const int wp = warp;
    if (wp >= NB) return;

    const bool act = (lane < Vv);
    float wrow[Vv];
    #pragma unroll
    for (int k = 0; k < Vv; k++) wrow[k] = 0.f;

    float dec_in = 0.f;
    float* op = out;
    if (act) {
        #pragma unroll
        for (int k = 0; k < Vv; k++) wrow[k] = __ldg(&Wd_hh[lane * Vv + k]);
        // dec_in = encoded @ Wd_ih[lane]^T + bd_ih + bd_hh (constant across steps).
        // Final encoder h is in c2[0] (step 2047 wrote buffer (2047+1)&1 = 0).
        const float* hc = reinterpret_cast<const float*>(&c2[0][wp][0]); // lo halves
        const float* wi = Wd_ih + (size_t)lane * Hh;
        float a0 = bd_ih[lane] + bd_hh[lane], a1 = 0.f, a2 = 0.f, a3 = 0.f;
        #pragma unroll
        for (int k = 0; k < Hh; k += 4) {
            a0 += hc[2 * (k + 0)] * __ldg(wi + k + 0);
            a1 += hc[2 * (k + 1)] * __ldg(wi + k + 1);
            a2 += hc[2 * (k + 2)] * __ldg(wi + k + 2);
            a3 += hc[2 * (k + 3)] * __ldg(wi + k + 3);
        }
        dec_in = (a0 + a1) + (a2 + a3);
        op = out + (size_t)(bbase + wp) * (Ss * Vv) + lane;
    }

    float hval = 0.f;   // inactive lanes stay exactly 0 (wrow=0, dec_in=0 -> tanh(0)=0)
    #pragma unroll 1
    for (int s = 0; s < Ss; s++) {
        float a0 = dec_in, a1 = 0.f, a2 = 0.f, a3 = 0.f;
        #pragma unroll
        for (int k = 0; k < 28; k += 4) {
            a0 += __shfl_sync(0xffffffffu, hval, k + 0) * wrow[k + 0];
            a1 += __shfl_sync(0xffffffffu, hval, k + 1) * wrow[k + 1];
            a2 += __shfl_sync(0xffffffffu, hval, k + 2) * wrow[k + 2];
            a3 += __shfl_sync(0xffffffffu, hval, k + 3) * wrow[k + 3];
        }
        a0 += __shfl_sync(0xffffffffu, hval, 28) * wrow[28];
        hval = tanh_acc((a0 + a1) + (a2 + a3));
        if (act) op[(size_t)s * Vv] = hval;
    }
}

extern "C" void kernel_launch(void* const* d_in, const int* in_sizes, int n_in,
                              void* d_out, int out_size) {
    (void)in_sizes; (void)n_in; (void)out_size;
    rnn_ae_kernel<<<Bb / NB, NTHREADS>>>(
        (const float*)d_in[0],  // x
        (const float*)d_in[1],  // We_ih
        (const float*)d_in[2],  // We_hh
        (const float*)d_in[3],  // be_ih
        (const float*)d_in[4],  // be_hh
        (const float*)d_in[5],  // Wd_ih
        (const float*)d_in[6],  // Wd_hh
        (const float*)d_in[7],  // bd_ih
        (const float*)d_in[8],  // bd_hh
        (float*)d_out);
}

// round 17
// speedup vs baseline: 1.1902x; 1.0064x over previous
#include <cuda_runtime.h>
#include <cstdint>
#include <cstddef>

#define Bb 512
#define Ss 2048
#define Vv 29
#define Hh 128
#define NB 2            // batch rows per block
#define NTHREADS 256
#define KTOT 157        // 128 (h) + 29 (x)
#define KQ 10           // k-range per 16-way slice (16*10 = 160 >= 157, tail zero-padded)
#define NPAIR 4         // output pairs per thread
#define CLEN 160        // padded concat vector length

using ull = unsigned long long;

__device__ __forceinline__ ull pack2(float lo, float hi) {
    ull r; asm("mov.b64 %0, {%1, %2};" : "=l"(r) : "f"(lo), "f"(hi)); return r;
}
__device__ __forceinline__ float2 unpack2(ull v) {
    float2 r; asm("mov.b64 {%0, %1}, %2;" : "=f"(r.x), "=f"(r.y) : "l"(v)); return r;
}
__device__ __forceinline__ ull fma2(ull a, ull b, ull c) {
    ull d; asm("fma.rn.f32x2 %0, %1, %2, %3;" : "=l"(d) : "l"(a), "l"(b), "l"(c)); return d;
}
__device__ __forceinline__ ull add2(ull a, ull b) {
    ull d; asm("add.rn.f32x2 %0, %1, %2;" : "=l"(d) : "l"(a), "l"(b)); return d;
}
__device__ __forceinline__ ull shfl_bfly2(ull v, int m) {
    uint32_t lo = (uint32_t)v, hi = (uint32_t)(v >> 32);
    lo = __shfl_xor_sync(0xffffffffu, lo, m);
    hi = __shfl_xor_sync(0xffffffffu, hi, m);
    return (ull)lo | ((ull)hi << 32);
}

// Accurate tanh via MUFU.EX2: abs error ~1e-7, safe for 2048-step recurrence.
__device__ __forceinline__ float tanh_acc(float xx) {
    float ax = fabsf(xx);
    float e  = __expf(-2.0f * ax);
    float r  = __fdividef(1.0f - e, 1.0f + e);
    return copysignf(r, xx);
}

__global__ void __launch_bounds__(NTHREADS, 2) rnn_ae_kernel(
    const float* __restrict__ x,
    const float* __restrict__ We_ih, const float* __restrict__ We_hh,
    const float* __restrict__ be_ih, const float* __restrict__ be_hh,
    const float* __restrict__ Wd_ih, const float* __restrict__ Wd_hh,
    const float* __restrict__ bd_ih, const float* __restrict__ bd_hh,
    float* __restrict__ out)
{
    // Double-buffered concat state, duplicated (v,v) fp32 pairs:
    // c2[buf][b][k]: k<128 -> h[k], 128..156 -> x[b,t,k-128], 157..159 -> permanent zeros.
    __shared__ __align__(16) ull c2[2][NB][CLEN];

    const int tid   = threadIdx.x;
    const int lane  = tid & 31;
    const int warp  = tid >> 5;        // jg_hi (3 bits)
    const int jg_lo = lane & 1;
    const int q     = lane >> 1;       // k-slice index, 0..15 (lane bits 1..4)
    const int jg    = warp * 2 + jg_lo;            // j-group 0..15 (4 pairs each)
    const int k0    = q * KQ;
    const int qb0   = q & 1, qb1 = (q >> 1) & 1, qb2 = (q >> 2) & 1, qb3 = (q >> 3) & 1;
    const int p_own = 2 * qb1 + qb2;   // which of my 4 pairs I own post-reduce
    const int r_own = qb0;             // which row
    const int half  = qb3;             // which scalar of the pair
    const int hidx  = 8 * jg + 2 * p_own + half;   // h unit index 0..127
    const int bbase = blockIdx.x * NB;

    // ---- recurrent weights -> registers: 4 pairs x 10 k = 40 packed ulls ----
    ull w2[NPAIR][KQ];
    #pragma unroll
    for (int p = 0; p < NPAIR; p++) {
        const int j0 = 2 * (jg * NPAIR + p), j1 = j0 + 1;
        #pragma unroll
        for (int kk = 0; kk < KQ; kk++) {
            int k = k0 + kk;
            float a0 = 0.f, a1 = 0.f;
            if (k < Hh)        { a0 = We_hh[j0 * Hh + k];        a1 = We_hh[j1 * Hh + k]; }
            else if (k < KTOT) { a0 = We_ih[j0 * Vv + (k - Hh)]; a1 = We_ih[j1 * Vv + (k - Hh)]; }
            w2[p][kk] = pack2(a0, a1);
        }
    }
    const float bias_me = be_ih[hidx] + be_hh[hidx];

    for (int i = tid; i < 2 * NB * CLEN; i += NTHREADS) (&c2[0][0][0])[i] = 0ull;
    __syncthreads();

    // x-prefetch duty: tids 0..57 each own one (row, vocab) slot
    const bool xact = (tid < NB * Vv);
    const int  xb   = xact ? (tid / Vv) : 0;
    const int  xv   = xact ? (tid % Vv) : 0;
    const float* xptr = x + (size_t)(bbase + xb) * (Ss * Vv) + xv;
    float xr = 0.f;
    if (xact) {
        float x0 = __ldg(xptr);
        c2[0][xb][Hh + xv] = pack2(x0, x0);
        xr = __ldg(xptr + Vv);          // x[t=1]
    }
    __syncthreads();

    // ================= encoder: 2048 sequential steps, 1 barrier each =================
    #pragma unroll 1
    for (int t = 0; t < Ss; t++) {
        const int cur = t & 1, nxt = cur ^ 1;

        // start the long-latency fetch of x[t+2] now; STAGE x[t+1] (xstage) later,
        // after the FMA-phase LDS reads, so no STS sits above them.
        float xstage = xr;
        if (xact && t + 2 < Ss) xr = __ldg(xptr + (size_t)(t + 2) * Vv);

        // ---- FMA phase: 10 LDS.128, 80 fma2 (4 pairs x 10 k x 2 rows) ----
        // One pointer for both rows: row 1 sits CLEN ulls (= CLEN/2 ulonglong2) away.
        ull acc[NPAIR][2];
        #pragma unroll
        for (int p = 0; p < NPAIR; p++) { acc[p][0] = 0ull; acc[p][1] = 0ull; }

        const ulonglong2* cp = reinterpret_cast<const ulonglong2*>(&c2[cur][0][k0]);
        #pragma unroll
        for (int g = 0; g < KQ / 2; g++) {
            ulonglong2 v0 = cp[g];
            ulonglong2 v1 = cp[g + CLEN / 2];
            #pragma unroll
            for (int p = 0; p < NPAIR; p++) {
                acc[p][0] = fma2(w2[p][2 * g],     v0.x, acc[p][0]);
                acc[p][0] = fma2(w2[p][2 * g + 1], v0.y, acc[p][0]);
                acc[p][1] = fma2(w2[p][2 * g],     v1.x, acc[p][1]);
                acc[p][1] = fma2(w2[p][2 * g + 1], v1.y, acc[p][1]);
            }
        }

        // stage x[t+1] into the buffer step t+1 will read (after all LDS of cur)
        if (xact && t + 1 < Ss) c2[nxt][xb][Hh + xv] = pack2(xstage, xstage);

        // ---- butterfly exchange-reduce over the 16 k-slices ----
        // stage 1 (mask 2): fold row dimension; lane keeps row r_own = qb0
        ull s1[NPAIR];
        #pragma unroll
        for (int p = 0; p < NPAIR; p++) {
            ull snd = qb0 ? acc[p][0] : acc[p][1];
            ull kp  = qb0 ? acc[p][1] : acc[p][0];
            s1[p] = add2(kp, shfl_bfly2(snd, 2));
        }
        // stage 2 (mask 4): fold p_hi; qb1 selects {2,3} vs {0,1}
        ull s2[2];
        #pragma unroll
        for (int i = 0; i < 2; i++) {
            ull snd = qb1 ? s1[i]     : s1[i + 2];
            ull kp  = qb1 ? s1[i + 2] : s1[i];
            s2[i] = add2(kp, shfl_bfly2(snd, 4));
        }
        // stage 3 (mask 8): fold p_lo; qb2 selects which of the remaining two
        {
            ull snd = qb2 ? s2[0] : s2[1];
            ull kp  = qb2 ? s2[1] : s2[0];
            ull s3  = add2(kp, shfl_bfly2(snd, 8));

            // stage 4 (mask 16): SCALAR exchange — send the component the partner
            // owns (1 - half), keep mine, one 32-bit shfl instead of two.
            float2 f3   = unpack2(s3);
            float  mine = half ? f3.y : f3.x;
            float  send = half ? f3.x : f3.y;
            float  recv = __shfl_xor_sync(0xffffffffu, send, 16);
            float  tv   = tanh_acc(mine + recv + bias_me);
            c2[nxt][r_own][hidx] = pack2(tv, tv);
        }
        __syncthreads();
    }

    // ================= decoder: warp-per-batch-row, shuffle-broadcast h =================
    // Warp wp (< NB) owns batch row bbase+wp; lane = vocab unit. No smem, no barriers.
    const int wp = warp;
    if (wp >= NB) return;

    const bool act = (lane < Vv);
    float wrow[Vv];
    #pragma unroll
    for (int k = 0; k < Vv; k++) wrow[k] = 0.f;

    float dec_in = 0.f;
    float* op = out;
    if (act) {
        #pragma unroll
        for (int k = 0; k < Vv; k++) wrow[k] = __ldg(&Wd_hh[lane * Vv + k]);
        // dec_in = encoded @ Wd_ih[lane]^T + bd_ih + bd_hh (constant across steps).
        // Final encoder h is in c2[0] (step 2047 wrote buffer (2047+1)&1 = 0).
        const float* hc = reinterpret_cast<const float*>(&c2[0][wp][0]); // lo halves
        const float* wi = Wd_ih + (size_t)lane * Hh;
        float a0 = bd_ih[lane] + bd_hh[lane], a1 = 0.f, a2 = 0.f, a3 = 0.f;
        #pragma unroll
        for (int k = 0; k < Hh; k += 4) {
            a0 += hc[2 * (k + 0)] * __ldg(wi + k + 0);
            a1 += hc[2 * (k + 1)] * __ldg(wi + k + 1);
            a2 += hc[2 * (k + 2)] * __ldg(wi + k + 2);
            a3 += hc[2 * (k + 3)] * __ldg(wi + k + 3);
        }
        dec_in = (a0 + a1) + (a2 + a3);
        op = out + (size_t)(bbase + wp) * (Ss * Vv) + lane;
    }

    float hval = 0.f;   // inactive lanes stay exactly 0 (wrow=0, dec_in=0 -> tanh(0)=0)
    #pragma unroll 1
    for (int s = 0; s < Ss; s++) {
        float a0 = dec_in, a1 = 0.f, a2 = 0.f, a3 = 0.f;
        #pragma unroll
        for (int k = 0; k < 28; k += 4) {
            a0 += __shfl_sync(0xffffffffu, hval, k + 0) * wrow[k + 0];
            a1 += __shfl_sync(0xffffffffu, hval, k + 1) * wrow[k + 1];
            a2 += __shfl_sync(0xffffffffu, hval, k + 2) * wrow[k + 2];
            a3 += __shfl_sync(0xffffffffu, hval, k + 3) * wrow[k + 3];
        }
        a0 += __shfl_sync(0xffffffffu, hval, 28) * wrow[28];
        hval = tanh_acc((a0 + a1) + (a2 + a3));
        if (act) op[(size_t)s * Vv] = hval;
    }
}

extern "C" void kernel_launch(void* const* d_in, const int* in_sizes, int n_in,
                              void* d_out, int out_size) {
    (void)in_sizes; (void)n_in; (void)out_size;
    rnn_ae_kernel<<<Bb / NB, NTHREADS>>>(
        (const float*)d_in[0],  // x
        (const float*)d_in[1],  // We_ih
        (const float*)d_in[2],  // We_hh
        (const float*)d_in[3],  // be_ih
        (const float*)d_in[4],  // be_hh
        (const float*)d_in[5],  // Wd_ih
        (const float*)d_in[6],  // Wd_hh
        (const float*)d_in[7],  // bd_ih
        (const float*)d_in[8],  // bd_hh
        (float*)d_out);
}